// round 8
// baseline (speedup 1.0000x reference)
#include <cuda_runtime.h>
#include <cuda_fp16.h>
#include <cstdint>

// ---------------------------------------------------------------------------
// Problem constants
// ---------------------------------------------------------------------------
#define N_SEL 256
#define PTS   2048
#define D_IN  256
#define D_OUT 256
#define TILES 8

// 32 MB fp16 scratch: gathered+transposed weights, layout [c][n][k]
static __device__ __half g_wt[(size_t)N_SEL * D_OUT * D_IN];

// ---------------------------------------------------------------------------
// Helpers (generic PTX only — compute_103 target has no tcgen05/TMA-a features)
// ---------------------------------------------------------------------------
#define SWZ128(o) ((o) ^ (((o) >> 3) & 0x70))

static __device__ __forceinline__ uint32_t smem_u32(const void* p) {
    uint32_t a;
    asm("{ .reg .u64 t; cvta.to.shared.u64 t, %1; cvt.u32.u64 %0, t; }"
        : "=r"(a) : "l"(p));
    return a;
}

static __device__ __forceinline__ void ldmx4(uint32_t* r, uint32_t addr) {
    asm volatile("ldmatrix.sync.aligned.m8n8.x4.shared.b16 {%0,%1,%2,%3}, [%4];"
                 : "=r"(r[0]), "=r"(r[1]), "=r"(r[2]), "=r"(r[3]) : "r"(addr));
}

static __device__ __forceinline__ void mma16816(float* c, const uint32_t* a,
                                                const uint32_t* b) {
    asm volatile(
        "mma.sync.aligned.m16n8k16.row.col.f32.f16.f16.f32 "
        "{%0,%1,%2,%3}, {%4,%5,%6,%7}, {%8,%9}, {%0,%1,%2,%3};"
        : "+f"(c[0]), "+f"(c[1]), "+f"(c[2]), "+f"(c[3])
        : "r"(a[0]), "r"(a[1]), "r"(a[2]), "r"(a[3]), "r"(b[0]), "r"(b[1]));
}

#define CP_ASYNC16(smem_addr, gptr) \
    asm volatile("cp.async.cg.shared.global [%0], [%1], 16;" \
                 :: "r"(smem_addr), "l"(gptr) : "memory")
#define CP_COMMIT() asm volatile("cp.async.commit_group;" ::: "memory")
#define CP_WAIT0()  asm volatile("cp.async.wait_group 0;" ::: "memory")

// ---------------------------------------------------------------------------
// indices may be int32 or int64 (JAX x64 flag unknown). For int64, the odd
// 32-bit words of non-negative values < 256 are all zero; for int32 random
// values in [0,256) they are almost surely not. P(misdetect) ~= 256^-16.
// ---------------------------------------------------------------------------
static __device__ __forceinline__ int sel_index(const void* idx_raw, int c) {
    const int* pi = (const int*)idx_raw;
    int odd_or = 0;
#pragma unroll
    for (int j = 0; j < 16; ++j) odd_or |= pi[2 * j + 1];
    return (odd_or == 0) ? pi[2 * c] : pi[c];
}

// ---------------------------------------------------------------------------
// Pre-pass: g_wt[c][n][k] = (half) weight[idx[c]][t][k][n]
// Grid: 256 channels x 8 k-tiles x 8 n-tiles, 256 threads, 32x32 smem tiles.
// ---------------------------------------------------------------------------
__global__ void __launch_bounds__(256) wt_gather_transpose_kernel(
    const float* __restrict__ weight,
    const void* __restrict__ idx_raw,
    const int* __restrict__ t_ptr)
{
    __shared__ float tile[32][33];
    int bid = blockIdx.x;
    int c = bid >> 6;
    int rem = bid & 63;
    int kt = rem >> 3, nt = rem & 7;

    int t = t_ptr ? *t_ptr : 3;   // low 32-bit word valid for int32 and int64
    int ch = sel_index(idx_raw, c);

    const float* src = weight + (((size_t)ch * TILES + t) << 16);
    int tx = threadIdx.x & 31, ty = threadIdx.x >> 5;

#pragma unroll
    for (int i = 0; i < 4; ++i)
        tile[ty + i * 8][tx] = src[(size_t)(kt * 32 + ty + i * 8) * 256 + nt * 32 + tx];
    __syncthreads();

    __half* dst = g_wt + (((size_t)c * 256 + nt * 32) << 8) + kt * 32;
#pragma unroll
    for (int i = 0; i < 4; ++i)
        dst[(size_t)(ty + i * 8) * 256 + tx] = __float2half_rn(tile[tx][ty + i * 8]);
}

// ---------------------------------------------------------------------------
// Main kernel: one CTA per (channel, 128-pt tile), FULL 256 output columns,
// processed as two sequential 128-col phases sharing one fully-resident
// 64 KB fp16 A tile (4 chunk slots of 128x64 halves, written once).
//   Phase 1: pipelined A fill (LDG fp32 -> cvt -> swizzled STS) + B cp.async
//   Phase 2: A resident; fragment-double-buffered LDSM/MMA pipeline
// 256 threads / 8 warps (4m x 2n), warp tile 32x64, mma.sync.m16n8k16.
// 2 CTAs/SM (<=128 regs, 98 KB smem each). x is read from GMEM exactly once.
// ---------------------------------------------------------------------------
#define OFF_A    0u          // 4 slots x 16384 B (slot kc at kc*16384)
#define OFF_B0   65536u
#define OFF_B1   81920u
#define OFF_BIAS 98304u      // 256 floats
#define SMEM_DYN (99328u + 1024u)   // + pad for 1024B alignment

__global__ void __launch_bounds__(256, 2)
adaptive_linear_main_kernel(
    const float* __restrict__ x,
    const float* __restrict__ bias,
    const void* __restrict__ idx_raw,
    const int* __restrict__ t_ptr,
    float* __restrict__ out)
{
    extern __shared__ char dyn_smem[];
    uint32_t raw = smem_u32(dyn_smem);
    uint32_t sb = (raw + 1023u) & ~1023u;      // 1024B-aligned base for SW128
    char* sp = dyn_smem + (sb - raw);

    int tid = threadIdx.x;
    int wid = tid >> 5, lid = tid & 31;
    int c  = blockIdx.y;
    int m0 = blockIdx.x * 128;

    int t = t_ptr ? *t_ptr : 3;
    int ch = sel_index(idx_raw, c);
    ((float*)(sp + OFF_BIAS))[tid] = bias[(((size_t)ch * TILES + t) << 8) + tid];

    const float*  xA = x + (((size_t)c * PTS + m0) << 8);
    const __half* wBase = g_wt + ((size_t)c << 16);

    // per-thread load mapping
    int arow = tid >> 2;            // A: 64 rows per half, 4 threads/row
    int aq   = tid & 3;             // 16-float segment within 64-float chunk
    int bn   = tid >> 1;            // B: 128 rows, 2 threads/row
    int bj0  = (tid & 1) * 4;       // 4 x 16B segments each

    float4 pa[4];                   // A prefetch registers (16 floats)

    // ---- A half-chunk LDG into regs (h = 0/1 selects 64-row half) ---------
    auto ldgA = [&](int kc, int h) {
        int r = h * 64 + arow;
        const float4* src = (const float4*)(xA + ((size_t)r << 8) + kc * 64 + aq * 16);
#pragma unroll
        for (int i = 0; i < 4; ++i) pa[i] = __ldcs(src + i);   // read-once stream
    };
    // ---- A regs -> fp16 swizzled STS into slot kc -------------------------
    auto stsA = [&](int kc, int h) {
        uint32_t abase = OFF_A + (uint32_t)kc * 16384u;
        uint32_t u[8];
#pragma unroll
        for (int i = 0; i < 4; ++i) {
            __half2 h0 = __floats2half2_rn(pa[i].x, pa[i].y);
            __half2 h1 = __floats2half2_rn(pa[i].z, pa[i].w);
            u[2 * i]     = *reinterpret_cast<uint32_t*>(&h0);
            u[2 * i + 1] = *reinterpret_cast<uint32_t*>(&h1);
        }
        uint32_t o = (uint32_t)((h * 64 + arow) * 128 + aq * 32);
        *reinterpret_cast<uint4*>(sp + abase + SWZ128(o)) =
            make_uint4(u[0], u[1], u[2], u[3]);
        *reinterpret_cast<uint4*>(sp + abase + SWZ128(o + 16)) =
            make_uint4(u[4], u[5], u[6], u[7]);
    };
    // ---- B chunk cp.async (phase p selects 128-col half of W) -------------
    auto cpB = [&](int p, int kc, uint32_t bbase) {
        const __half* wB = wBase + ((size_t)p << 15);
#pragma unroll
        for (int i = 0; i < 4; ++i) {
            int j = bj0 + i;
            uint32_t o = (uint32_t)(bn * 128 + j * 16);
            const __half* g = wB + ((size_t)bn << 8) + kc * 64 + j * 8;
            CP_ASYNC16(sb + bbase + SWZ128(o), g);
        }
    };

    // warp tile origin (8 warps: 4 m x 2 n)
    int mrow0 = (wid & 3) * 32;
    int ncol0 = (wid >> 2) * 64;
    // ldmatrix per-lane bases
    uint32_t aRow  = (uint32_t)(mrow0 + (lid & 15));
    uint32_t aKoff = (uint32_t)((lid >> 4) * 16);          // bytes
    uint32_t bRow  = (uint32_t)(ncol0 + ((lid >> 4) << 3) + (lid & 7));
    uint32_t bKoff = (uint32_t)(((lid >> 3) & 1) * 16);    // bytes

    float acc[2][8][4];
    auto zero_acc = [&]() {
#pragma unroll
        for (int mt = 0; mt < 2; ++mt)
#pragma unroll
            for (int nt = 0; nt < 8; ++nt)
#pragma unroll
                for (int r = 0; r < 4; ++r) acc[mt][nt][r] = 0.f;
    };

    // ---- fragment load (6 x ldmx4) for k-step ks of chunk kc --------------
    auto load_frags = [&](int kc, uint32_t bb, int ks,
                          uint32_t (*a)[4], uint32_t (*b)[4]) {
        uint32_t ab = sb + OFF_A + (uint32_t)kc * 16384u;
#pragma unroll
        for (int mt = 0; mt < 2; ++mt) {
            uint32_t o = (aRow + mt * 16) * 128 + ks * 32 + aKoff;
            ldmx4(a[mt], ab + SWZ128(o));
        }
#pragma unroll
        for (int p = 0; p < 4; ++p) {
            uint32_t o = (bRow + p * 16) * 128 + ks * 32 + bKoff;
            ldmx4(b[p], bb + SWZ128(o));
        }
    };
    auto mma_block = [&](uint32_t (*a)[4], uint32_t (*b)[4]) {
#pragma unroll
        for (int mt = 0; mt < 2; ++mt)
#pragma unroll
            for (int nt = 0; nt < 8; ++nt)
                mma16816(acc[mt][nt], a[mt], &b[nt >> 1][(nt & 1) * 2]);
    };
    // ---- non-pipelined k-step (phase 1, where pa regs are live) -----------
    auto compute_ks = [&](int kc, uint32_t bb, int ks) {
        uint32_t a[2][4], b[4][4];
        load_frags(kc, bb, ks, a, b);
        mma_block(a, b);
    };

    // ---- epilogue: accums + bias -> GMEM for column base nb ---------------
    auto epilogue = [&](int nb) {
        const float* bsm = (const float*)(sp + OFF_BIAS);
        int r0 = lid >> 2;
        int c0 = 2 * (lid & 3);
#pragma unroll
        for (int mt = 0; mt < 2; ++mt) {
            size_t rowg = (size_t)c * PTS + m0 + mrow0 + mt * 16 + r0;
#pragma unroll
            for (int nt = 0; nt < 8; ++nt) {
                int col = nb + ncol0 + nt * 8 + c0;
                float b0 = bsm[col], b1 = bsm[col + 1];
                float2 v0 = make_float2(acc[mt][nt][0] + b0, acc[mt][nt][1] + b1);
                float2 v1 = make_float2(acc[mt][nt][2] + b0, acc[mt][nt][3] + b1);
                __stcs(reinterpret_cast<float2*>(out + (rowg << 8) + col), v0);
                __stcs(reinterpret_cast<float2*>(out + ((rowg + 8) << 8) + col), v1);
            }
        }
    };

    zero_acc();

    // ---- prologue: A chunk 0 + B(phase0, chunk0) --------------------------
    cpB(0, 0, OFF_B0);
    CP_COMMIT();
    ldgA(0, 0);
    stsA(0, 0);
    ldgA(0, 1);
    stsA(0, 1);
    CP_WAIT0();
    __syncthreads();

    // ---- phase 1: compute n-cols [0,128) while filling A ------------------
    for (int kc = 0; kc < 4; ++kc) {
        uint32_t bb  = sb + ((kc & 1) ? OFF_B1 : OFF_B0);
        uint32_t bbN = (kc & 1) ? OFF_B0 : OFF_B1;

        if (kc < 3) {
            cpB(0, kc + 1, bbN);
            CP_COMMIT();
        } else {
            // buf0 idle since end of kc==2 (sync passed): preload phase-2 ch0
            cpB(1, 0, OFF_B0);
            CP_COMMIT();
        }

        compute_ks(kc, bb, 0);
        if (kc < 3) ldgA(kc + 1, 0);
        compute_ks(kc, bb, 1);
        if (kc < 3) { stsA(kc + 1, 0); ldgA(kc + 1, 1); }
        compute_ks(kc, bb, 2);
        if (kc < 3) stsA(kc + 1, 1);
        compute_ks(kc, bb, 3);

        if (kc < 3) {
            CP_WAIT0();
            __syncthreads();
        }
    }

    // accs complete (registers) — overlap STG with the in-flight cp.async
    epilogue(0);
    zero_acc();
    CP_WAIT0();
    __syncthreads();

    // ---- phase 2: n-cols [128,256); A resident; frag double buffering -----
    for (int kc = 0; kc < 4; ++kc) {
        uint32_t bb  = sb + ((kc & 1) ? OFF_B1 : OFF_B0);
        uint32_t bbN = (kc & 1) ? OFF_B0 : OFF_B1;

        if (kc < 3) {
            cpB(1, kc + 1, bbN);
            CP_COMMIT();
        }

        // software-pipelined fragments: LDSM for ks+1 issued before MMAs of ks
        uint32_t af[2][2][4], bf[2][4][4];
        load_frags(kc, bb, 0, af[0], bf[0]);
#pragma unroll
        for (int ks = 0; ks < 4; ++ks) {
            int cur = ks & 1, nxt = cur ^ 1;
            if (ks < 3) load_frags(kc, bb, ks + 1, af[nxt], bf[nxt]);
            mma_block(af[cur], bf[cur]);
        }

        if (kc < 3) {
            CP_WAIT0();
            __syncthreads();
        }
    }

    epilogue(128);
}

// ---------------------------------------------------------------------------
// kernel_launch: pre-pass (gather/transpose/convert weights) then main GEMM.
// Inputs (metadata order): x, weight, bias, indices, t
// ---------------------------------------------------------------------------
extern "C" void kernel_launch(void* const* d_in, const int* in_sizes, int n_in,
                              void* d_out, int out_size)
{
    const float* x       = (const float*)d_in[0];
    const float* weight  = (const float*)d_in[1];
    const float* bias    = (const float*)d_in[2];
    const void*  indices = d_in[3];
    const int*   t_ptr   = (n_in >= 5) ? (const int*)d_in[4] : nullptr;
    float* out = (float*)d_out;

    cudaFuncSetAttribute(adaptive_linear_main_kernel,
                         cudaFuncAttributeMaxDynamicSharedMemorySize, SMEM_DYN);

    wt_gather_transpose_kernel<<<N_SEL * 64, 256>>>(weight, indices, t_ptr);
    adaptive_linear_main_kernel<<<dim3(16, N_SEL), 256, SMEM_DYN>>>(
        x, bias, indices, t_ptr, out);
}

// round 9
// speedup vs baseline: 1.0396x; 1.0396x over previous
#include <cuda_runtime.h>
#include <cuda_fp16.h>
#include <cstdint>

// ---------------------------------------------------------------------------
// Problem constants
// ---------------------------------------------------------------------------
#define N_SEL 256
#define PTS   2048
#define D_IN  256
#define D_OUT 256
#define TILES 8

// 32 MB fp16 scratch: gathered+transposed weights, layout [c][n][k]
static __device__ __half g_wt[(size_t)N_SEL * D_OUT * D_IN];

// ---------------------------------------------------------------------------
// Helpers (generic PTX only — compute_103 target has no tcgen05/TMA-a features)
// ---------------------------------------------------------------------------
#define SWZ128(o) ((o) ^ (((o) >> 3) & 0x70))

static __device__ __forceinline__ uint32_t smem_u32(const void* p) {
    uint32_t a;
    asm("{ .reg .u64 t; cvta.to.shared.u64 t, %1; cvt.u32.u64 %0, t; }"
        : "=r"(a) : "l"(p));
    return a;
}

static __device__ __forceinline__ void ldmx4(uint32_t* r, uint32_t addr) {
    asm volatile("ldmatrix.sync.aligned.m8n8.x4.shared.b16 {%0,%1,%2,%3}, [%4];"
                 : "=r"(r[0]), "=r"(r[1]), "=r"(r[2]), "=r"(r[3]) : "r"(addr));
}

static __device__ __forceinline__ void mma16816(float* c, const uint32_t* a,
                                                const uint32_t* b) {
    asm volatile(
        "mma.sync.aligned.m16n8k16.row.col.f32.f16.f16.f32 "
        "{%0,%1,%2,%3}, {%4,%5,%6,%7}, {%8,%9}, {%0,%1,%2,%3};"
        : "+f"(c[0]), "+f"(c[1]), "+f"(c[2]), "+f"(c[3])
        : "r"(a[0]), "r"(a[1]), "r"(a[2]), "r"(a[3]), "r"(b[0]), "r"(b[1]));
}

#define CP_ASYNC16(smem_addr, gptr) \
    asm volatile("cp.async.cg.shared.global [%0], [%1], 16;" \
                 :: "r"(smem_addr), "l"(gptr) : "memory")
#define CP_COMMIT() asm volatile("cp.async.commit_group;" ::: "memory")
#define CP_WAIT0()  asm volatile("cp.async.wait_group 0;" ::: "memory")
#define PREFETCH_L2(p) \
    asm volatile("prefetch.global.L2 [%0];" :: "l"(p))

// ---------------------------------------------------------------------------
// indices may be int32 or int64 (JAX x64 flag unknown). For int64, the odd
// 32-bit words of non-negative values < 256 are all zero; for int32 random
// values in [0,256) they are almost surely not. P(misdetect) ~= 256^-16.
// ---------------------------------------------------------------------------
static __device__ __forceinline__ int sel_index(const void* idx_raw, int c) {
    const int* pi = (const int*)idx_raw;
    int odd_or = 0;
#pragma unroll
    for (int j = 0; j < 16; ++j) odd_or |= pi[2 * j + 1];
    return (odd_or == 0) ? pi[2 * c] : pi[c];
}

// ---------------------------------------------------------------------------
// Pre-pass: g_wt[c][n][k] = (half) weight[idx[c]][t][k][n]
// Grid: 256 channels x 8 k-tiles x 8 n-tiles, 256 threads, 32x32 smem tiles.
// ---------------------------------------------------------------------------
__global__ void __launch_bounds__(256) wt_gather_transpose_kernel(
    const float* __restrict__ weight,
    const void* __restrict__ idx_raw,
    const int* __restrict__ t_ptr)
{
    __shared__ float tile[32][33];
    int bid = blockIdx.x;
    int c = bid >> 6;
    int rem = bid & 63;
    int kt = rem >> 3, nt = rem & 7;

    int t = t_ptr ? *t_ptr : 3;   // low 32-bit word valid for int32 and int64
    int ch = sel_index(idx_raw, c);

    const float* src = weight + (((size_t)ch * TILES + t) << 16);
    int tx = threadIdx.x & 31, ty = threadIdx.x >> 5;

#pragma unroll
    for (int i = 0; i < 4; ++i)
        tile[ty + i * 8][tx] = src[(size_t)(kt * 32 + ty + i * 8) * 256 + nt * 32 + tx];
    __syncthreads();

    __half* dst = g_wt + (((size_t)c * 256 + nt * 32) << 8) + kt * 32;
#pragma unroll
    for (int i = 0; i < 4; ++i)
        dst[(size_t)(ty + i * 8) * 256 + tx] = __float2half_rn(tile[tx][ty + i * 8]);
}

// ---------------------------------------------------------------------------
// Main kernel: one CTA per (channel, 128-pt tile), FULL 256 output columns,
// processed as two sequential 128-col phases sharing one fully-resident
// 64 KB fp16 A tile (4 chunk slots of 128x64 halves, written once).
//   Phase 1: pipelined A fill (LDG fp32 -> cvt -> swizzled STS) + B cp.async;
//            next A chunk is prefetched into L2 a full chunk ahead so the
//            interleaved LDGs are ~L2-hit latency, covered by the compute.
//   Phase 2: A resident; pure B-pipeline + LDSM + MMA
// 256 threads / 8 warps (4m x 2n), warp tile 32x64, mma.sync.m16n8k16.
// 2 CTAs/SM (<=128 regs, 98 KB smem each). x is read from GMEM exactly once.
// ---------------------------------------------------------------------------
#define OFF_A    0u          // 4 slots x 16384 B (slot kc at kc*16384)
#define OFF_B0   65536u
#define OFF_B1   81920u
#define OFF_BIAS 98304u      // 256 floats
#define SMEM_DYN (99328u + 1024u)   // + pad for 1024B alignment

__global__ void __launch_bounds__(256, 2)
adaptive_linear_main_kernel(
    const float* __restrict__ x,
    const float* __restrict__ bias,
    const void* __restrict__ idx_raw,
    const int* __restrict__ t_ptr,
    float* __restrict__ out)
{
    extern __shared__ char dyn_smem[];
    uint32_t raw = smem_u32(dyn_smem);
    uint32_t sb = (raw + 1023u) & ~1023u;      // 1024B-aligned base for SW128
    char* sp = dyn_smem + (sb - raw);

    int tid = threadIdx.x;
    int wid = tid >> 5, lid = tid & 31;
    int c  = blockIdx.y;
    int m0 = blockIdx.x * 128;

    int t = t_ptr ? *t_ptr : 3;
    int ch = sel_index(idx_raw, c);
    ((float*)(sp + OFF_BIAS))[tid] = bias[(((size_t)ch * TILES + t) << 8) + tid];

    const float*  xA = x + (((size_t)c * PTS + m0) << 8);
    const __half* wBase = g_wt + ((size_t)c << 16);

    // per-thread load mapping
    int arow = tid >> 2;            // A: 64 rows per half, 4 threads/row
    int aq   = tid & 3;             // 16-float segment within 64-float chunk
    int bn   = tid >> 1;            // B: 128 rows, 2 threads/row
    int bj0  = (tid & 1) * 4;       // 4 x 16B segments each

    float4 pa[4];                   // A prefetch registers (16 floats)

    // ---- prefetch A chunk kc into L2 (256 x 128B lines, 1 line/thread) ----
    auto prefA = [&](int kc) {
        const float* p = xA + ((size_t)(tid >> 1) << 8) + kc * 64 + (tid & 1) * 32;
        PREFETCH_L2(p);
    };
    // ---- A half-chunk LDG into regs (h = 0/1 selects 64-row half) ---------
    auto ldgA = [&](int kc, int h) {
        int r = h * 64 + arow;
        const float4* src = (const float4*)(xA + ((size_t)r << 8) + kc * 64 + aq * 16);
#pragma unroll
        for (int i = 0; i < 4; ++i) pa[i] = src[i];
    };
    // ---- A regs -> fp16 swizzled STS into slot kc -------------------------
    auto stsA = [&](int kc, int h) {
        uint32_t abase = OFF_A + (uint32_t)kc * 16384u;
        uint32_t u[8];
#pragma unroll
        for (int i = 0; i < 4; ++i) {
            __half2 h0 = __floats2half2_rn(pa[i].x, pa[i].y);
            __half2 h1 = __floats2half2_rn(pa[i].z, pa[i].w);
            u[2 * i]     = *reinterpret_cast<uint32_t*>(&h0);
            u[2 * i + 1] = *reinterpret_cast<uint32_t*>(&h1);
        }
        uint32_t o = (uint32_t)((h * 64 + arow) * 128 + aq * 32);
        *reinterpret_cast<uint4*>(sp + abase + SWZ128(o)) =
            make_uint4(u[0], u[1], u[2], u[3]);
        *reinterpret_cast<uint4*>(sp + abase + SWZ128(o + 16)) =
            make_uint4(u[4], u[5], u[6], u[7]);
    };
    // ---- B chunk cp.async (phase p selects 128-col half of W) -------------
    auto cpB = [&](int p, int kc, uint32_t bbase) {
        const __half* wB = wBase + ((size_t)p << 15);
#pragma unroll
        for (int i = 0; i < 4; ++i) {
            int j = bj0 + i;
            uint32_t o = (uint32_t)(bn * 128 + j * 16);
            const __half* g = wB + ((size_t)bn << 8) + kc * 64 + j * 8;
            CP_ASYNC16(sb + bbase + SWZ128(o), g);
        }
    };

    // warp tile origin (8 warps: 4 m x 2 n)
    int mrow0 = (wid & 3) * 32;
    int ncol0 = (wid >> 2) * 64;
    // ldmatrix per-lane bases
    uint32_t aRow  = (uint32_t)(mrow0 + (lid & 15));
    uint32_t aKoff = (uint32_t)((lid >> 4) * 16);          // bytes
    uint32_t bRow  = (uint32_t)(ncol0 + ((lid >> 4) << 3) + (lid & 7));
    uint32_t bKoff = (uint32_t)(((lid >> 3) & 1) * 16);    // bytes

    float acc[2][8][4];
    auto zero_acc = [&]() {
#pragma unroll
        for (int mt = 0; mt < 2; ++mt)
#pragma unroll
            for (int nt = 0; nt < 8; ++nt)
#pragma unroll
                for (int r = 0; r < 4; ++r) acc[mt][nt][r] = 0.f;
    };

    // ---- one 16-wide k-step of chunk kc ------------------------------------
    auto compute_ks = [&](int kc, uint32_t bb, int ks) {
        uint32_t ab = sb + OFF_A + (uint32_t)kc * 16384u;
        uint32_t a[2][4];
#pragma unroll
        for (int mt = 0; mt < 2; ++mt) {
            uint32_t o = (aRow + mt * 16) * 128 + ks * 32 + aKoff;
            ldmx4(a[mt], ab + SWZ128(o));
        }
        uint32_t b[4][4];
#pragma unroll
        for (int p = 0; p < 4; ++p) {
            uint32_t o = (bRow + p * 16) * 128 + ks * 32 + bKoff;
            ldmx4(b[p], bb + SWZ128(o));
        }
#pragma unroll
        for (int mt = 0; mt < 2; ++mt)
#pragma unroll
            for (int nt = 0; nt < 8; ++nt)
                mma16816(acc[mt][nt], a[mt], &b[nt >> 1][(nt & 1) * 2]);
    };

    // ---- epilogue: accums + bias -> GMEM for column base nb ---------------
    auto epilogue = [&](int nb) {
        const float* bsm = (const float*)(sp + OFF_BIAS);
        int r0 = lid >> 2;
        int c0 = 2 * (lid & 3);
#pragma unroll
        for (int mt = 0; mt < 2; ++mt) {
            size_t rowg = (size_t)c * PTS + m0 + mrow0 + mt * 16 + r0;
#pragma unroll
            for (int nt = 0; nt < 8; ++nt) {
                int col = nb + ncol0 + nt * 8 + c0;
                float b0 = bsm[col], b1 = bsm[col + 1];
                float2 v0 = make_float2(acc[mt][nt][0] + b0, acc[mt][nt][1] + b1);
                float2 v1 = make_float2(acc[mt][nt][2] + b0, acc[mt][nt][3] + b1);
                __stcs(reinterpret_cast<float2*>(out + (rowg << 8) + col), v0);
                __stcs(reinterpret_cast<float2*>(out + ((rowg + 8) << 8) + col), v1);
            }
        }
    };

    zero_acc();

    // ---- prologue: A chunk 0 + B(phase0, chunk0) --------------------------
    cpB(0, 0, OFF_B0);
    CP_COMMIT();
    prefA(1);                       // chunk 1 -> L2 while chunk 0 LDGs run
    ldgA(0, 0);
    stsA(0, 0);
    ldgA(0, 1);
    stsA(0, 1);
    CP_WAIT0();
    __syncthreads();

    // ---- phase 1: compute n-cols [0,128) while filling A ------------------
    for (int kc = 0; kc < 4; ++kc) {
        uint32_t bb  = sb + ((kc & 1) ? OFF_B1 : OFF_B0);
        uint32_t bbN = (kc & 1) ? OFF_B0 : OFF_B1;

        if (kc < 3) {
            cpB(0, kc + 1, bbN);
            CP_COMMIT();
            if (kc < 2) prefA(kc + 2);   // stay one full chunk ahead in L2
        } else {
            // buf0 idle since end of kc==2 (sync passed): preload phase-2 ch0
            cpB(1, 0, OFF_B0);
            CP_COMMIT();
        }

        compute_ks(kc, bb, 0);
        if (kc < 3) ldgA(kc + 1, 0);
        compute_ks(kc, bb, 1);
        if (kc < 3) { stsA(kc + 1, 0); ldgA(kc + 1, 1); }
        compute_ks(kc, bb, 2);
        if (kc < 3) stsA(kc + 1, 1);
        compute_ks(kc, bb, 3);

        if (kc < 3) {
            CP_WAIT0();
            __syncthreads();
        }
    }

    // accs complete (registers) — overlap STG with the in-flight cp.async
    epilogue(0);
    zero_acc();
    CP_WAIT0();
    __syncthreads();

    // ---- phase 2: compute n-cols [128,256); A fully resident --------------
    for (int kc = 0; kc < 4; ++kc) {
        uint32_t bb  = sb + ((kc & 1) ? OFF_B1 : OFF_B0);
        uint32_t bbN = (kc & 1) ? OFF_B0 : OFF_B1;

        if (kc < 3) {
            cpB(1, kc + 1, bbN);
            CP_COMMIT();
        }

        compute_ks(kc, bb, 0);
        compute_ks(kc, bb, 1);
        compute_ks(kc, bb, 2);
        compute_ks(kc, bb, 3);

        if (kc < 3) {
            CP_WAIT0();
            __syncthreads();
        }
    }

    epilogue(128);
}

// ---------------------------------------------------------------------------
// kernel_launch: pre-pass (gather/transpose/convert weights) then main GEMM.
// Inputs (metadata order): x, weight, bias, indices, t
// ---------------------------------------------------------------------------
extern "C" void kernel_launch(void* const* d_in, const int* in_sizes, int n_in,
                              void* d_out, int out_size)
{
    const float* x       = (const float*)d_in[0];
    const float* weight  = (const float*)d_in[1];
    const float* bias    = (const float*)d_in[2];
    const void*  indices = d_in[3];
    const int*   t_ptr   = (n_in >= 5) ? (const int*)d_in[4] : nullptr;
    float* out = (float*)d_out;

    cudaFuncSetAttribute(adaptive_linear_main_kernel,
                         cudaFuncAttributeMaxDynamicSharedMemorySize, SMEM_DYN);

    wt_gather_transpose_kernel<<<N_SEL * 64, 256>>>(weight, indices, t_ptr);
    adaptive_linear_main_kernel<<<dim3(16, N_SEL), 256, SMEM_DYN>>>(
        x, bias, indices, t_ptr, out);
}

// round 10
// speedup vs baseline: 1.4848x; 1.4282x over previous
#include <cuda_runtime.h>
#include <cuda_fp16.h>
#include <cstdint>

// ---------------------------------------------------------------------------
// Problem constants
// ---------------------------------------------------------------------------
#define N_SEL 256
#define PTS   2048
#define D_IN  256
#define D_OUT 256
#define TILES 8

// 32 MB fp16 scratch: gathered+transposed weights, layout [c][n][k]
static __device__ __half g_wt[(size_t)N_SEL * D_OUT * D_IN];

// ---------------------------------------------------------------------------
// Helpers (generic PTX only — compute_103 target has no tcgen05/TMA-a features)
// ---------------------------------------------------------------------------
#define SWZ128(o) ((o) ^ (((o) >> 3) & 0x70))

static __device__ __forceinline__ uint32_t smem_u32(const void* p) {
    uint32_t a;
    asm("{ .reg .u64 t; cvta.to.shared.u64 t, %1; cvt.u32.u64 %0, t; }"
        : "=r"(a) : "l"(p));
    return a;
}

static __device__ __forceinline__ void ldmx4(uint32_t* r, uint32_t addr) {
    asm volatile("ldmatrix.sync.aligned.m8n8.x4.shared.b16 {%0,%1,%2,%3}, [%4];"
                 : "=r"(r[0]), "=r"(r[1]), "=r"(r[2]), "=r"(r[3]) : "r"(addr));
}

static __device__ __forceinline__ void mma16816(float* c, const uint32_t* a,
                                                const uint32_t* b) {
    asm volatile(
        "mma.sync.aligned.m16n8k16.row.col.f32.f16.f16.f32 "
        "{%0,%1,%2,%3}, {%4,%5,%6,%7}, {%8,%9}, {%0,%1,%2,%3};"
        : "+f"(c[0]), "+f"(c[1]), "+f"(c[2]), "+f"(c[3])
        : "r"(a[0]), "r"(a[1]), "r"(a[2]), "r"(a[3]), "r"(b[0]), "r"(b[1]));
}

#define CP_ASYNC16(smem_addr, gptr) \
    asm volatile("cp.async.cg.shared.global [%0], [%1], 16;" \
                 :: "r"(smem_addr), "l"(gptr) : "memory")
#define CP_COMMIT() asm volatile("cp.async.commit_group;" ::: "memory")
#define CP_WAIT0()  asm volatile("cp.async.wait_group 0;" ::: "memory")

// ---------------------------------------------------------------------------
// indices may be int32 or int64 (JAX x64 flag unknown). For int64, the odd
// 32-bit words of non-negative values < 256 are all zero; for int32 random
// values in [0,256) they are almost surely not. P(misdetect) ~= 256^-16.
// ---------------------------------------------------------------------------
static __device__ __forceinline__ int sel_index(const void* idx_raw, int c) {
    const int* pi = (const int*)idx_raw;
    int odd_or = 0;
#pragma unroll
    for (int j = 0; j < 16; ++j) odd_or |= pi[2 * j + 1];
    return (odd_or == 0) ? pi[2 * c] : pi[c];
}

// ---------------------------------------------------------------------------
// Pre-pass: g_wt[c][n][k] = (half) weight[idx[c]][t][k][n]
// Grid: 256 channels x 8 k-tiles x 8 n-tiles, 256 threads, 32x32 smem tiles.
// ---------------------------------------------------------------------------
__global__ void __launch_bounds__(256) wt_gather_transpose_kernel(
    const float* __restrict__ weight,
    const void* __restrict__ idx_raw,
    const int* __restrict__ t_ptr)
{
    __shared__ float tile[32][33];
    int bid = blockIdx.x;
    int c = bid >> 6;
    int rem = bid & 63;
    int kt = rem >> 3, nt = rem & 7;

    int t = t_ptr ? *t_ptr : 3;   // low 32-bit word valid for int32 and int64
    int ch = sel_index(idx_raw, c);

    const float* src = weight + (((size_t)ch * TILES + t) << 16);
    int tx = threadIdx.x & 31, ty = threadIdx.x >> 5;

#pragma unroll
    for (int i = 0; i < 4; ++i)
        tile[ty + i * 8][tx] = src[(size_t)(kt * 32 + ty + i * 8) * 256 + nt * 32 + tx];
    __syncthreads();

    __half* dst = g_wt + (((size_t)c * 256 + nt * 32) << 8) + kt * 32;
#pragma unroll
    for (int i = 0; i < 4; ++i)
        dst[(size_t)(ty + i * 8) * 256 + tx] = __float2half_rn(tile[tx][ty + i * 8]);
}

// ---------------------------------------------------------------------------
// Main kernel: one CTA per (channel, 128-pt tile), FULL 256 output columns,
// processed as two sequential 128-col phases sharing one fully-resident
// 64 KB fp16 A tile (4 chunk slots of 128x64 halves, written once).
//   Phase 1: pipelined A fill (LDG fp32 -> cvt -> swizzled STS) + B cp.async.
//            Each A half-chunk LDG is issued TWO compute blocks before its
//            STS consumes it (covers most of the DRAM latency; reg-neutral:
//            one 16-reg half in flight at a time).
//   Phase 2: A resident; pure B-pipeline + LDSM + MMA
// 256 threads / 8 warps (4m x 2n), warp tile 32x64, mma.sync.m16n8k16.
// 2 CTAs/SM (<=128 regs, 98 KB smem each). x is read from GMEM exactly once.
// ---------------------------------------------------------------------------
#define OFF_A    0u          // 4 slots x 16384 B (slot kc at kc*16384)
#define OFF_B0   65536u
#define OFF_B1   81920u
#define OFF_BIAS 98304u      // 256 floats
#define SMEM_DYN (99328u + 1024u)   // + pad for 1024B alignment

__global__ void __launch_bounds__(256, 2)
adaptive_linear_main_kernel(
    const float* __restrict__ x,
    const float* __restrict__ bias,
    const void* __restrict__ idx_raw,
    const int* __restrict__ t_ptr,
    float* __restrict__ out)
{
    extern __shared__ char dyn_smem[];
    uint32_t raw = smem_u32(dyn_smem);
    uint32_t sb = (raw + 1023u) & ~1023u;      // 1024B-aligned base for SW128
    char* sp = dyn_smem + (sb - raw);

    int tid = threadIdx.x;
    int wid = tid >> 5, lid = tid & 31;
    int c  = blockIdx.y;
    int m0 = blockIdx.x * 128;

    int t = t_ptr ? *t_ptr : 3;
    int ch = sel_index(idx_raw, c);
    ((float*)(sp + OFF_BIAS))[tid] = bias[(((size_t)ch * TILES + t) << 8) + tid];

    const float*  xA = x + (((size_t)c * PTS + m0) << 8);
    const __half* wBase = g_wt + ((size_t)c << 16);

    // per-thread load mapping
    int arow = tid >> 2;            // A: 64 rows per half, 4 threads/row
    int aq   = tid & 3;             // 16-float segment within 64-float chunk
    int bn   = tid >> 1;            // B: 128 rows, 2 threads/row
    int bj0  = (tid & 1) * 4;       // 4 x 16B segments each

    float4 pa[4];                   // A prefetch registers (16 floats)

    // ---- A half-chunk LDG into regs (h = 0/1 selects 64-row half) ---------
    auto ldgA = [&](int kc, int h) {
        int r = h * 64 + arow;
        const float4* src = (const float4*)(xA + ((size_t)r << 8) + kc * 64 + aq * 16);
#pragma unroll
        for (int i = 0; i < 4; ++i) pa[i] = src[i];
    };
    // ---- A regs -> fp16 swizzled STS into slot kc -------------------------
    auto stsA = [&](int kc, int h) {
        uint32_t abase = OFF_A + (uint32_t)kc * 16384u;
        uint32_t u[8];
#pragma unroll
        for (int i = 0; i < 4; ++i) {
            __half2 h0 = __floats2half2_rn(pa[i].x, pa[i].y);
            __half2 h1 = __floats2half2_rn(pa[i].z, pa[i].w);
            u[2 * i]     = *reinterpret_cast<uint32_t*>(&h0);
            u[2 * i + 1] = *reinterpret_cast<uint32_t*>(&h1);
        }
        uint32_t o = (uint32_t)((h * 64 + arow) * 128 + aq * 32);
        *reinterpret_cast<uint4*>(sp + abase + SWZ128(o)) =
            make_uint4(u[0], u[1], u[2], u[3]);
        *reinterpret_cast<uint4*>(sp + abase + SWZ128(o + 16)) =
            make_uint4(u[4], u[5], u[6], u[7]);
    };
    // ---- B chunk cp.async (phase p selects 128-col half of W) -------------
    auto cpB = [&](int p, int kc, uint32_t bbase) {
        const __half* wB = wBase + ((size_t)p << 15);
#pragma unroll
        for (int i = 0; i < 4; ++i) {
            int j = bj0 + i;
            uint32_t o = (uint32_t)(bn * 128 + j * 16);
            const __half* g = wB + ((size_t)bn << 8) + kc * 64 + j * 8;
            CP_ASYNC16(sb + bbase + SWZ128(o), g);
        }
    };

    // warp tile origin (8 warps: 4 m x 2 n)
    int mrow0 = (wid & 3) * 32;
    int ncol0 = (wid >> 2) * 64;
    // ldmatrix per-lane bases
    uint32_t aRow  = (uint32_t)(mrow0 + (lid & 15));
    uint32_t aKoff = (uint32_t)((lid >> 4) * 16);          // bytes
    uint32_t bRow  = (uint32_t)(ncol0 + ((lid >> 4) << 3) + (lid & 7));
    uint32_t bKoff = (uint32_t)(((lid >> 3) & 1) * 16);    // bytes

    float acc[2][8][4];
    auto zero_acc = [&]() {
#pragma unroll
        for (int mt = 0; mt < 2; ++mt)
#pragma unroll
            for (int nt = 0; nt < 8; ++nt)
#pragma unroll
                for (int r = 0; r < 4; ++r) acc[mt][nt][r] = 0.f;
    };

    // ---- one 16-wide k-step of chunk kc ------------------------------------
    // LDSM/MMA interleaved: a0,a1,b0,b1 loads -> 8 MMAs -> b2,b3 loads -> 8 MMAs.
    // First MMA starts after 4 LDSM (not 6); b2/b3 latency hides under MMAs.
    auto compute_ks = [&](int kc, uint32_t bb, int ks) {
        uint32_t ab = sb + OFF_A + (uint32_t)kc * 16384u;
        uint32_t a[2][4];
        uint32_t b[4][4];
#pragma unroll
        for (int mt = 0; mt < 2; ++mt) {
            uint32_t o = (aRow + mt * 16) * 128 + ks * 32 + aKoff;
            ldmx4(a[mt], ab + SWZ128(o));
        }
#pragma unroll
        for (int p = 0; p < 2; ++p) {
            uint32_t o = (bRow + p * 16) * 128 + ks * 32 + bKoff;
            ldmx4(b[p], bb + SWZ128(o));
        }
#pragma unroll
        for (int mt = 0; mt < 2; ++mt)
#pragma unroll
            for (int nt = 0; nt < 4; ++nt)
                mma16816(acc[mt][nt], a[mt], &b[nt >> 1][(nt & 1) * 2]);
#pragma unroll
        for (int p = 2; p < 4; ++p) {
            uint32_t o = (bRow + p * 16) * 128 + ks * 32 + bKoff;
            ldmx4(b[p], bb + SWZ128(o));
        }
#pragma unroll
        for (int mt = 0; mt < 2; ++mt)
#pragma unroll
            for (int nt = 4; nt < 8; ++nt)
                mma16816(acc[mt][nt], a[mt], &b[nt >> 1][(nt & 1) * 2]);
    };

    // ---- epilogue: accums + bias -> GMEM for column base nb ---------------
    auto epilogue = [&](int nb) {
        const float* bsm = (const float*)(sp + OFF_BIAS);
        int r0 = lid >> 2;
        int c0 = 2 * (lid & 3);
#pragma unroll
        for (int mt = 0; mt < 2; ++mt) {
            size_t rowg = (size_t)c * PTS + m0 + mrow0 + mt * 16 + r0;
#pragma unroll
            for (int nt = 0; nt < 8; ++nt) {
                int col = nb + ncol0 + nt * 8 + c0;
                float b0 = bsm[col], b1 = bsm[col + 1];
                float2 v0 = make_float2(acc[mt][nt][0] + b0, acc[mt][nt][1] + b1);
                float2 v1 = make_float2(acc[mt][nt][2] + b0, acc[mt][nt][3] + b1);
                *reinterpret_cast<float2*>(out + (rowg << 8) + col) = v0;
                *reinterpret_cast<float2*>(out + ((rowg + 8) << 8) + col) = v1;
            }
        }
    };

    zero_acc();

    // ---- prologue: A chunk 0 + B(phase0, chunk0) --------------------------
    cpB(0, 0, OFF_B0);
    CP_COMMIT();
    ldgA(0, 0);
    stsA(0, 0);
    ldgA(0, 1);
    stsA(0, 1);
    CP_WAIT0();
    __syncthreads();

    // ---- phase 1: compute n-cols [0,128) while filling A ------------------
    for (int kc = 0; kc < 4; ++kc) {
        uint32_t bb  = sb + ((kc & 1) ? OFF_B1 : OFF_B0);
        uint32_t bbN = (kc & 1) ? OFF_B0 : OFF_B1;

        if (kc < 3) {
            cpB(0, kc + 1, bbN);
            CP_COMMIT();
        } else {
            // buf0 idle since end of kc==2 (sync passed): preload phase-2 ch0
            cpB(1, 0, OFF_B0);
            CP_COMMIT();
        }

        // A half-chunk LDGs issued two compute blocks ahead of their STS
        if (kc < 3) ldgA(kc + 1, 0);
        compute_ks(kc, bb, 0);
        compute_ks(kc, bb, 1);
        if (kc < 3) { stsA(kc + 1, 0); ldgA(kc + 1, 1); }
        compute_ks(kc, bb, 2);
        compute_ks(kc, bb, 3);

        if (kc < 3) {
            stsA(kc + 1, 1);
            CP_WAIT0();
            __syncthreads();
        }
    }

    // accs complete (registers) — overlap STG with the in-flight cp.async
    epilogue(0);
    zero_acc();
    CP_WAIT0();
    __syncthreads();

    // ---- phase 2: compute n-cols [128,256); A fully resident --------------
    for (int kc = 0; kc < 4; ++kc) {
        uint32_t bb  = sb + ((kc & 1) ? OFF_B1 : OFF_B0);
        uint32_t bbN = (kc & 1) ? OFF_B0 : OFF_B1;

        if (kc < 3) {
            cpB(1, kc + 1, bbN);
            CP_COMMIT();
        }

        compute_ks(kc, bb, 0);
        compute_ks(kc, bb, 1);
        compute_ks(kc, bb, 2);
        compute_ks(kc, bb, 3);

        if (kc < 3) {
            CP_WAIT0();
            __syncthreads();
        }
    }

    epilogue(128);
}

// ---------------------------------------------------------------------------
// kernel_launch: pre-pass (gather/transpose/convert weights) then main GEMM.
// Inputs (metadata order): x, weight, bias, indices, t
// ---------------------------------------------------------------------------
extern "C" void kernel_launch(void* const* d_in, const int* in_sizes, int n_in,
                              void* d_out, int out_size)
{
    const float* x       = (const float*)d_in[0];
    const float* weight  = (const float*)d_in[1];
    const float* bias    = (const float*)d_in[2];
    const void*  indices = d_in[3];
    const int*   t_ptr   = (n_in >= 5) ? (const int*)d_in[4] : nullptr;
    float* out = (float*)d_out;

    cudaFuncSetAttribute(adaptive_linear_main_kernel,
                         cudaFuncAttributeMaxDynamicSharedMemorySize, SMEM_DYN);

    wt_gather_transpose_kernel<<<N_SEL * 64, 256>>>(weight, indices, t_ptr);
    adaptive_linear_main_kernel<<<dim3(16, N_SEL), 256, SMEM_DYN>>>(
        x, bias, indices, t_ptr, out);
}